// round 6
// baseline (speedup 1.0000x reference)
#include <cuda_runtime.h>
#include <cuda_fp16.h>

#define NN 100000
#define EE 1200000
#define HH 64
#define BB 1000
#define CC 10
#define BN_EPS 1e-5f
#define PAD 65   // padded row stride in shared buf (floats)

typedef unsigned long long u64;

// Scratch (device globals; no allocation allowed)
__device__ __align__(16) __half g_xh[NN * HH];       // fp16 shadow of x
__device__ __align__(16) __half g_h1bh[NN * HH];     // fp16 output of MLP1
__device__ __align__(16) float  g_xstruct[BB * HH];  // pooled per-graph features
__device__ int g_deg[NN];
__device__ int g_rowptr[NN + 1];
__device__ int g_cursor[NN];
__device__ int g_bsum[512];
__device__ int g_csr[EE];

__device__ __forceinline__ void red_add_v4(float* p, float4 v) {
    asm volatile("red.global.add.v4.f32 [%0], {%1,%2,%3,%4};"
                 :: "l"(p), "f"(v.x), "f"(v.y), "f"(v.z), "f"(v.w)
                 : "memory");
}

__device__ __forceinline__ u64 pack2(float lo, float hi) {
    u64 r;
    asm("mov.b64 %0, {%1,%2};" : "=l"(r) : "f"(lo), "f"(hi));
    return r;
}
__device__ __forceinline__ void unpack2(u64 v, float& lo, float& hi) {
    asm("mov.b64 {%0,%1}, %2;" : "=f"(lo), "=f"(hi) : "l"(v));
}
__device__ __forceinline__ void ffma2(u64& d, u64 a, u64 b) {
    asm("fma.rn.f32x2 %0, %1, %2, %0;" : "+l"(d) : "l"(a), "l"(b));
}

// ---------------------------------------------------------------------------
// Prep: zero deg + xstruct, convert x -> fp16 shadow table.
// ---------------------------------------------------------------------------
__global__ void prep_kernel(const float* __restrict__ x) {
    int i = blockIdx.x * 256 + threadIdx.x;
    if (i < NN) g_deg[i] = 0;
    if (i < BB * HH) g_xstruct[i] = 0.0f;
    if (i < NN * HH / 4) {
        float4 v = *(const float4*)(x + (size_t)i * 4);
        __half2 h0 = __floats2half2_rn(v.x, v.y);
        __half2 h1 = __floats2half2_rn(v.z, v.w);
        uint2 u;
        u.x = *(unsigned*)&h0;
        u.y = *(unsigned*)&h1;
        *(uint2*)(g_xh + (size_t)i * 4) = u;
    }
}

__global__ void hist_kernel(const int* __restrict__ ei) {
    int e = blockIdx.x * 256 + threadIdx.x;
    if (e < EE) atomicAdd(&g_deg[ei[EE + e]], 1);
}

__global__ void bsum_kernel() {   // 391 blocks x 256, raw block sums
    __shared__ int sh[256];
    int i = blockIdx.x * 256 + threadIdx.x;
    int t = threadIdx.x;
    sh[t] = (i < NN) ? g_deg[i] : 0;
    __syncthreads();
    for (int off = 128; off > 0; off >>= 1) {
        if (t < off) sh[t] += sh[t + off];
        __syncthreads();
    }
    if (t == 0) g_bsum[blockIdx.x] = sh[0];
}

// rowptr: inline prefix over raw block sums
__global__ void rowptr_kernel() {   // 391 blocks x 256
    __shared__ int sh[256];
    __shared__ int red[256];
    int i = blockIdx.x * 256 + threadIdx.x;
    int t = threadIdx.x;

    int pre = 0;
    for (int b = t; b < blockIdx.x; b += 256) pre += g_bsum[b];
    red[t] = pre;
    __syncthreads();
    for (int off = 128; off > 0; off >>= 1) {
        if (t < off) red[t] += red[t + off];
        __syncthreads();
    }
    int base = red[0];

    int v = (i < NN) ? g_deg[i] : 0;
    sh[t] = v;
    __syncthreads();
    for (int off = 1; off < 256; off <<= 1) {
        int a = (t >= off) ? sh[t - off] : 0;
        __syncthreads();
        sh[t] += a;
        __syncthreads();
    }
    if (i < NN) {
        int r = base + sh[t] - v;   // exclusive
        g_rowptr[i] = r;
        g_cursor[i] = r;
    }
    if (i == 0) g_rowptr[NN] = EE;
}

__global__ void scatter_kernel(const int* __restrict__ ei) {
    int e = blockIdx.x * 256 + threadIdx.x;
    if (e < EE) {
        int s = ei[e];
        int d = ei[EE + e];
        int pos = atomicAdd(&g_cursor[d], 1);
        g_csr[pos] = s;
    }
}

// ---------------------------------------------------------------------------
// Fused gather helper: warp-per-row gather into smem buf.
// Lane owns cols (2*lane, 2*lane+1). Neighbors from fp16 table, fp32 accum.
// SELF_FP32: self term read from fp32 x; else from the fp16 table itself.
// ---------------------------------------------------------------------------
template<bool SELF_FP32>
__device__ __forceinline__ void gather_tile(
    float* buf, const float* __restrict__ xf, const __half* __restrict__ tab,
    int n0, int tid)
{
    const int w    = tid >> 5;    // warp 0..3
    const int lane = tid & 31;
    for (int r = w; r < 128; r += 4) {
        int node = n0 + r;
        if (node >= NN) break;
        float a0, a1;
        if (SELF_FP32) {
            float2 s = *(const float2*)(xf + (size_t)node * 64 + 2 * lane);
            a0 = s.x; a1 = s.y;
        } else {
            __half2 h = *(const __half2*)(tab + (size_t)node * 64 + 2 * lane);
            float2 s = __half22float2(h);
            a0 = s.x; a1 = s.y;
        }
        int j = g_rowptr[node];
        int e = g_rowptr[node + 1];
        for (; j + 3 < e; j += 4) {
            int s0 = g_csr[j],     s1 = g_csr[j + 1];
            int s2 = g_csr[j + 2], s3 = g_csr[j + 3];
            float2 f0 = __half22float2(*(const __half2*)(tab + (size_t)s0 * 64 + 2 * lane));
            float2 f1 = __half22float2(*(const __half2*)(tab + (size_t)s1 * 64 + 2 * lane));
            float2 f2 = __half22float2(*(const __half2*)(tab + (size_t)s2 * 64 + 2 * lane));
            float2 f3 = __half22float2(*(const __half2*)(tab + (size_t)s3 * 64 + 2 * lane));
            a0 += (f0.x + f1.x) + (f2.x + f3.x);
            a1 += (f0.y + f1.y) + (f2.y + f3.y);
        }
        for (; j < e; j++) {
            int s0 = g_csr[j];
            float2 f0 = __half22float2(*(const __half2*)(tab + (size_t)s0 * 64 + 2 * lane));
            a0 += f0.x; a1 += f0.y;
        }
        buf[r * PAD + 2 * lane]     = a0;
        buf[r * PAD + 2 * lane + 1] = a1;
    }
}

// ---------------------------------------------------------------------------
// K3 fused: agg1 (in-place gather) + MLP1 -> g_h1bh (fp16)
// ---------------------------------------------------------------------------
__global__ __launch_bounds__(128) void mlp1_fused_kernel(
    const float* __restrict__ x,
    const float* __restrict__ W1a, const float* __restrict__ b1a,
    const float* __restrict__ g1,  const float* __restrict__ be1,
    const float* __restrict__ m1,  const float* __restrict__ v1,
    const float* __restrict__ W1b, const float* __restrict__ b1b)
{
    extern __shared__ float sm[];
    float* Wa  = sm;                 // 4096 floats
    float* Wb  = sm + 4096;          // 4096 floats
    float* buf = sm + 8192;          // 128*PAD floats
    __shared__ float bias1[64], bias2[64], scl[64];

    const int tid = threadIdx.x;
    const int tx  = tid & 7;    // col group
    const int ty  = tid >> 3;   // row group

    if (tid < 64) {
        float s = g1[tid] * rsqrtf(v1[tid] + BN_EPS);
        scl[tid]   = s;
        bias1[tid] = b1a[tid] * s + be1[tid] - m1[tid] * s;
        bias2[tid] = b1b[tid];
    }
    __syncthreads();
    for (int i = tid; i < 4096; i += 128) {
        Wa[i] = W1a[i] * scl[i & 63];
        Wb[i] = W1b[i];
    }
    __syncthreads();

    u64 b1p[4], b2p[4];
    #pragma unroll
    for (int c = 0; c < 4; c++) {
        b1p[c] = pack2(bias1[tx * 8 + 2 * c], bias1[tx * 8 + 2 * c + 1]);
        b2p[c] = pack2(bias2[tx * 8 + 2 * c], bias2[tx * 8 + 2 * c + 1]);
    }

    for (int n0 = blockIdx.x * 128; n0 < NN; n0 += gridDim.x * 128) {
        __syncthreads();
        gather_tile<true>(buf, x, g_xh, n0, tid);
        __syncthreads();

        // ---- layer 1 ----
        u64 acc[8][4];
        #pragma unroll
        for (int j = 0; j < 8; j++)
            #pragma unroll
            for (int c = 0; c < 4; c++) acc[j][c] = b1p[c];

        #pragma unroll 8
        for (int k = 0; k < 64; k++) {
            const u64* wr = (const u64*)(Wa + k * 64 + tx * 8);
            u64 w0 = wr[0], w1 = wr[1], w2 = wr[2], w3 = wr[3];
            #pragma unroll
            for (int j = 0; j < 8; j++) {
                float rv = buf[(ty * 8 + j) * PAD + k];
                u64 rp = pack2(rv, rv);
                ffma2(acc[j][0], rp, w0);
                ffma2(acc[j][1], rp, w1);
                ffma2(acc[j][2], rp, w2);
                ffma2(acc[j][3], rp, w3);
            }
        }
        __syncthreads();

        #pragma unroll
        for (int j = 0; j < 8; j++) {
            float* p = buf + (ty * 8 + j) * PAD + tx * 8;
            #pragma unroll
            for (int c = 0; c < 4; c++) {
                float lo, hi;
                unpack2(acc[j][c], lo, hi);
                p[2 * c]     = fmaxf(lo, 0.f);
                p[2 * c + 1] = fmaxf(hi, 0.f);
            }
        }
        __syncthreads();

        // ---- layer 2 ----
        u64 a2[8][4];
        #pragma unroll
        for (int j = 0; j < 8; j++)
            #pragma unroll
            for (int c = 0; c < 4; c++) a2[j][c] = b2p[c];

        #pragma unroll 8
        for (int k = 0; k < 64; k++) {
            const u64* wr = (const u64*)(Wb + k * 64 + tx * 8);
            u64 w0 = wr[0], w1 = wr[1], w2 = wr[2], w3 = wr[3];
            #pragma unroll
            for (int j = 0; j < 8; j++) {
                float rv = buf[(ty * 8 + j) * PAD + k];
                u64 rp = pack2(rv, rv);
                ffma2(a2[j][0], rp, w0);
                ffma2(a2[j][1], rp, w1);
                ffma2(a2[j][2], rp, w2);
                ffma2(a2[j][3], rp, w3);
            }
        }

        // relu -> fp16 -> store 8 cols (16 B) per row
        #pragma unroll
        for (int j = 0; j < 8; j++) {
            int node = n0 + ty * 8 + j;
            if (node >= NN) break;
            unsigned uu[4];
            #pragma unroll
            for (int c = 0; c < 4; c++) {
                float lo, hi;
                unpack2(a2[j][c], lo, hi);
                __half2 h = __floats2half2_rn(fmaxf(lo, 0.f), fmaxf(hi, 0.f));
                uu[c] = *(unsigned*)&h;
            }
            uint4 pack;
            pack.x = uu[0]; pack.y = uu[1]; pack.z = uu[2]; pack.w = uu[3];
            *(uint4*)(g_h1bh + (size_t)node * 64 + tx * 8) = pack;
        }
    }
}

// ---------------------------------------------------------------------------
// K5 fused: agg2 (in-place gather from g_h1bh) + MLP2 + pooling
// ---------------------------------------------------------------------------
__global__ __launch_bounds__(128) void mlp2_fused_kernel(
    const float* __restrict__ W2, const float* __restrict__ b2,
    const float* __restrict__ g2, const float* __restrict__ be2,
    const float* __restrict__ m2, const float* __restrict__ v2,
    const int* __restrict__ batch)
{
    extern __shared__ float sm[];
    float* Ws  = sm;                 // 4096 floats
    float* buf = sm + 4096;          // 128*PAD floats
    __shared__ float bias[64], scl[64];

    const int tid = threadIdx.x;
    const int tx  = tid & 7;
    const int ty  = tid >> 3;

    if (tid < 64) {
        float s = g2[tid] * rsqrtf(v2[tid] + BN_EPS);
        scl[tid]  = s;
        bias[tid] = b2[tid] * s + be2[tid] - m2[tid] * s;
    }
    __syncthreads();
    for (int i = tid; i < 4096; i += 128)
        Ws[i] = W2[i] * scl[i & 63];
    __syncthreads();

    u64 bp[4];
    #pragma unroll
    for (int c = 0; c < 4; c++)
        bp[c] = pack2(bias[tx * 8 + 2 * c], bias[tx * 8 + 2 * c + 1]);

    for (int n0 = blockIdx.x * 128; n0 < NN; n0 += gridDim.x * 128) {
        __syncthreads();
        gather_tile<false>(buf, (const float*)0, g_h1bh, n0, tid);
        __syncthreads();

        u64 acc[8][4];
        #pragma unroll
        for (int j = 0; j < 8; j++)
            #pragma unroll
            for (int c = 0; c < 4; c++) acc[j][c] = bp[c];

        #pragma unroll 8
        for (int k = 0; k < 64; k++) {
            const u64* wr = (const u64*)(Ws + k * 64 + tx * 8);
            u64 w0 = wr[0], w1 = wr[1], w2 = wr[2], w3 = wr[3];
            #pragma unroll
            for (int j = 0; j < 8; j++) {
                float rv = buf[(ty * 8 + j) * PAD + k];
                u64 rp = pack2(rv, rv);
                ffma2(acc[j][0], rp, w0);
                ffma2(acc[j][1], rp, w1);
                ffma2(acc[j][2], rp, w2);
                ffma2(acc[j][3], rp, w3);
            }
        }

        #pragma unroll
        for (int j = 0; j < 8; j++) {
            int node = n0 + ty * 8 + j;
            if (node >= NN) break;
            float o[8];
            #pragma unroll
            for (int c = 0; c < 4; c++) {
                unpack2(acc[j][c], o[2 * c], o[2 * c + 1]);
                o[2 * c]     = fmaxf(o[2 * c], 0.f);
                o[2 * c + 1] = fmaxf(o[2 * c + 1], 0.f);
            }
            int g = batch[node];
            float* dst = g_xstruct + (size_t)g * 64 + tx * 8;
            red_add_v4(dst,     make_float4(o[0], o[1], o[2], o[3]));
            red_add_v4(dst + 4, make_float4(o[4], o[5], o[6], o[7]));
        }
    }
}

// ---------------------------------------------------------------------------
// K6: x_topo = relu(topo @ Wt + bt); out = [xstruct, x_topo] @ Wc + bc
// ---------------------------------------------------------------------------
__global__ __launch_bounds__(256) void final_kernel(
    const float* __restrict__ topo, const float* __restrict__ Wt,
    const float* __restrict__ bt,   const float* __restrict__ Wc,
    const float* __restrict__ bc,   float* __restrict__ out)
{
    __shared__ float Wts[64 * 64];
    __shared__ float Wcs[128 * CC];
    __shared__ float bts[64], bcs[CC];
    __shared__ float trow[4][64];
    __shared__ float xt[4][64];
    __shared__ float xs[4][64];

    const int tx = threadIdx.x;   // 0..63
    const int ty = threadIdx.y;   // 0..3
    const int tid = ty * 64 + tx;

    for (int i = tid; i < 4096; i += 256) Wts[i] = Wt[i];
    for (int i = tid; i < 128 * CC; i += 256) Wcs[i] = Wc[i];
    if (tid < 64) bts[tid] = bt[tid];
    if (tid < CC) bcs[tid] = bc[tid];
    __syncthreads();

    for (int g0 = blockIdx.x * 4; g0 < BB; g0 += gridDim.x * 4) {
        int g = g0 + ty;
        bool valid = g < BB;
        if (valid) {
            trow[ty][tx] = topo[g * 64 + tx];
            xs[ty][tx]   = g_xstruct[g * 64 + tx];
        }
        __syncthreads();
        if (valid) {
            float acc = bts[tx];
            #pragma unroll 16
            for (int k = 0; k < 64; k++)
                acc += trow[ty][k] * Wts[k * 64 + tx];
            xt[ty][tx] = fmaxf(acc, 0.f);
        }
        __syncthreads();
        if (valid && tx < CC) {
            float acc = bcs[tx];
            #pragma unroll 16
            for (int k = 0; k < 64; k++) {
                acc += xs[ty][k] * Wcs[k * CC + tx];
                acc += xt[ty][k] * Wcs[(64 + k) * CC + tx];
            }
            out[g * CC + tx] = acc;
        }
        __syncthreads();
    }
}

// ---------------------------------------------------------------------------
extern "C" void kernel_launch(void* const* d_in, const int* in_sizes, int n_in,
                              void* d_out, int out_size) {
    const float* x    = (const float*)d_in[0];
    const int*   ei   = (const int*)d_in[1];
    const int*   batch= (const int*)d_in[2];
    const float* topo = (const float*)d_in[3];
    const float* W1a  = (const float*)d_in[4];
    const float* b1a  = (const float*)d_in[5];
    const float* g1   = (const float*)d_in[6];
    const float* be1  = (const float*)d_in[7];
    const float* m1   = (const float*)d_in[8];
    const float* v1   = (const float*)d_in[9];
    const float* W1b  = (const float*)d_in[10];
    const float* b1b  = (const float*)d_in[11];
    const float* W2   = (const float*)d_in[12];
    const float* b2   = (const float*)d_in[13];
    const float* g2   = (const float*)d_in[14];
    const float* be2  = (const float*)d_in[15];
    const float* m2   = (const float*)d_in[16];
    const float* v2   = (const float*)d_in[17];
    const float* Wt   = (const float*)d_in[18];
    const float* bt   = (const float*)d_in[19];
    const float* Wc   = (const float*)d_in[20];
    const float* bc   = (const float*)d_in[21];
    float* out = (float*)d_out;

    const int smem1 = (4096 + 4096 + 128 * PAD) * (int)sizeof(float);  // ~66 KB
    const int smem2 = (4096 + 128 * PAD) * (int)sizeof(float);         // ~50 KB
    static bool attr_set = false;
    if (!attr_set) {
        cudaFuncSetAttribute(mlp1_fused_kernel,
                             cudaFuncAttributeMaxDynamicSharedMemorySize, smem1);
        cudaFuncSetAttribute(mlp2_fused_kernel,
                             cudaFuncAttributeMaxDynamicSharedMemorySize, smem2);
        attr_set = true;
    }

    const int NB = (NN + 255) / 256;         // 391
    dim3 finBlock(64, 4);

    // CSR build + fp16 conversion
    prep_kernel<<<(NN * HH / 4 + 255) / 256, 256>>>(x);
    hist_kernel<<<(EE + 255) / 256, 256>>>(ei);
    bsum_kernel<<<NB, 256>>>();
    rowptr_kernel<<<NB, 256>>>();
    scatter_kernel<<<(EE + 255) / 256, 256>>>(ei);

    // Layer 1 (gather + MLP fused)
    mlp1_fused_kernel<<<444, 128, smem1>>>(x, W1a, b1a, g1, be1, m1, v1, W1b, b1b);

    // Layer 2 (gather + MLP + pool fused)
    mlp2_fused_kernel<<<444, 128, smem2>>>(W2, b2, g2, be2, m2, v2, batch);

    final_kernel<<<64, finBlock>>>(topo, Wt, bt, Wc, bc, out);
}

// round 7
// speedup vs baseline: 1.6047x; 1.6047x over previous
#include <cuda_runtime.h>
#include <cuda_fp16.h>
#include <mma.h>

using namespace nvcuda;

#define NN 100000
#define EE 1200000
#define HH 64
#define BB 1000
#define CC 10
#define BN_EPS 1e-5f

typedef unsigned long long u64;

// Scratch (device globals; no allocation allowed)
__device__ __align__(16) __half g_xh[NN * HH];       // fp16 shadow of x
__device__ __align__(16) __half g_agg1h[NN * HH];    // fp16 agg of layer 1 input
__device__ __align__(16) __half g_h1bh[NN * HH];     // fp16 output of MLP1
__device__ __align__(16) __half g_agg2h[NN * HH];    // fp16 agg of layer 2 input
__device__ __align__(16) float  g_xstruct[BB * HH];  // pooled per-graph features
__device__ int g_deg[NN];
__device__ int g_rowptr[NN + 1];
__device__ int g_epos[EE];
__device__ int g_bsum[512];
__device__ int g_csr[EE];

__device__ __forceinline__ void red_add_v4(float* p, float4 v) {
    asm volatile("red.global.add.v4.f32 [%0], {%1,%2,%3,%4};"
                 :: "l"(p), "f"(v.x), "f"(v.y), "f"(v.z), "f"(v.w)
                 : "memory");
}

// ---------------------------------------------------------------------------
// Prep: zero deg + xstruct, convert x -> fp16 shadow table.
// ---------------------------------------------------------------------------
__global__ void prep_kernel(const float* __restrict__ x) {
    int i = blockIdx.x * 256 + threadIdx.x;
    if (i < NN) g_deg[i] = 0;
    if (i < BB * HH) g_xstruct[i] = 0.0f;
    if (i < NN * HH / 4) {
        float4 v = *(const float4*)(x + (size_t)i * 4);
        __half2 h0 = __floats2half2_rn(v.x, v.y);
        __half2 h1 = __floats2half2_rn(v.z, v.w);
        uint2 u;
        u.x = *(unsigned*)&h0;
        u.y = *(unsigned*)&h1;
        *(uint2*)(g_xh + (size_t)i * 4) = u;
    }
}

// hist: degree count + record per-edge position within its dst row
__global__ void hist_kernel(const int* __restrict__ ei) {
    int e = blockIdx.x * 256 + threadIdx.x;
    if (e < EE) {
        int d = ei[EE + e];
        g_epos[e] = atomicAdd(&g_deg[d], 1);
    }
}

__global__ void bsum_kernel() {   // 391 blocks x 256, raw block sums
    __shared__ int sh[256];
    int i = blockIdx.x * 256 + threadIdx.x;
    int t = threadIdx.x;
    sh[t] = (i < NN) ? g_deg[i] : 0;
    __syncthreads();
    for (int off = 128; off > 0; off >>= 1) {
        if (t < off) sh[t] += sh[t + off];
        __syncthreads();
    }
    if (t == 0) g_bsum[blockIdx.x] = sh[0];
}

// rowptr: inline prefix over raw block sums
__global__ void rowptr_kernel() {   // 391 blocks x 256
    __shared__ int sh[256];
    __shared__ int red[256];
    int i = blockIdx.x * 256 + threadIdx.x;
    int t = threadIdx.x;

    int pre = 0;
    for (int b = t; b < blockIdx.x; b += 256) pre += g_bsum[b];
    red[t] = pre;
    __syncthreads();
    for (int off = 128; off > 0; off >>= 1) {
        if (t < off) red[t] += red[t + off];
        __syncthreads();
    }
    int base = red[0];

    int v = (i < NN) ? g_deg[i] : 0;
    sh[t] = v;
    __syncthreads();
    for (int off = 1; off < 256; off <<= 1) {
        int a = (t >= off) ? sh[t - off] : 0;
        __syncthreads();
        sh[t] += a;
        __syncthreads();
    }
    if (i < NN) g_rowptr[i] = base + sh[t] - v;   // exclusive
    if (i == 0) g_rowptr[NN] = EE;
}

// scatter without atomics: position precomputed in hist
__global__ void scatter_kernel(const int* __restrict__ ei) {
    int e = blockIdx.x * 256 + threadIdx.x;
    if (e < EE) {
        int s = ei[e];
        int d = ei[EE + e];
        g_csr[g_rowptr[d] + g_epos[e]] = s;
    }
}

// ---------------------------------------------------------------------------
// Pull aggregation, fp16 neighbor gather, fp32 accumulate, fp16 output.
// 16 threads per node, each owns 4 columns (8 B per row). No atomics.
// ---------------------------------------------------------------------------
__device__ __forceinline__ void acc_half4(float4& acc, const __half* base) {
    uint2 u = *(const uint2*)base;
    __half2 h0 = *(__half2*)&u.x;
    __half2 h1 = *(__half2*)&u.y;
    float2 f0 = __half22float2(h0);
    float2 f1 = __half22float2(h1);
    acc.x += f0.x; acc.y += f0.y; acc.z += f1.x; acc.w += f1.y;
}

__device__ __forceinline__ void store_half4(__half* p, float4 v) {
    __half2 h0 = __floats2half2_rn(v.x, v.y);
    __half2 h1 = __floats2half2_rn(v.z, v.w);
    uint2 u;
    u.x = *(unsigned*)&h0;
    u.y = *(unsigned*)&h1;
    *(uint2*)p = u;
}

__global__ __launch_bounds__(256) void agg1_kernel(const float* __restrict__ x)
{
    int tid = blockIdx.x * 256 + threadIdx.x;
    int node = tid >> 4;
    if (node >= NN) return;
    int c = (tid & 15) * 4;

    float4 acc = *(const float4*)(x + (size_t)node * 64 + c);  // self fp32
    int j = g_rowptr[node];
    int e = g_rowptr[node + 1];
    for (; j + 1 < e; j += 2) {
        int s0 = g_csr[j], s1 = g_csr[j + 1];
        acc_half4(acc, g_xh + (size_t)s0 * 64 + c);
        acc_half4(acc, g_xh + (size_t)s1 * 64 + c);
    }
    if (j < e) {
        int s0 = g_csr[j];
        acc_half4(acc, g_xh + (size_t)s0 * 64 + c);
    }
    store_half4(g_agg1h + (size_t)node * 64 + c, acc);
}

__global__ __launch_bounds__(256) void agg2_kernel()
{
    int tid = blockIdx.x * 256 + threadIdx.x;
    int node = tid >> 4;
    if (node >= NN) return;
    int c = (tid & 15) * 4;

    float4 acc = make_float4(0.f, 0.f, 0.f, 0.f);
    acc_half4(acc, g_h1bh + (size_t)node * 64 + c);   // self
    int j = g_rowptr[node];
    int e = g_rowptr[node + 1];
    for (; j + 1 < e; j += 2) {
        int s0 = g_csr[j], s1 = g_csr[j + 1];
        acc_half4(acc, g_h1bh + (size_t)s0 * 64 + c);
        acc_half4(acc, g_h1bh + (size_t)s1 * 64 + c);
    }
    if (j < e) {
        int s0 = g_csr[j];
        acc_half4(acc, g_h1bh + (size_t)s0 * 64 + c);
    }
    store_half4(g_agg2h + (size_t)node * 64 + c, acc);
}

// ---------------------------------------------------------------------------
// MLP1 (wmma): h1bh = fp16(relu( relu(BN(agg1 @ W1a + b1a)) @ W1b + b1b ))
// 128 threads = 4 warps. Tile = 128 nodes. A/B fp16, acc fp32.
// Dyn smem: Wa[4096]h + Wb[4096]h + Ah[8192]h + Mid[8192]f = 64 KB.
// ---------------------------------------------------------------------------
__global__ __launch_bounds__(128) void mlp1_kernel(
    const float* __restrict__ W1a, const float* __restrict__ b1a,
    const float* __restrict__ g1,  const float* __restrict__ be1,
    const float* __restrict__ m1,  const float* __restrict__ v1,
    const float* __restrict__ W1b, const float* __restrict__ b1b)
{
    extern __shared__ char smraw[];
    __half* Wa  = (__half*)smraw;            // 64x64
    __half* Wb  = Wa + 4096;                 // 64x64
    __half* Ah  = Wb + 4096;                 // 128x64
    float*  Mid = (float*)(Ah + 8192);       // 128x64
    __shared__ float bias1[64], bias2[64], scl[64];

    const int tid  = threadIdx.x;
    const int w    = tid >> 5;

    if (tid < 64) {
        float s = g1[tid] * rsqrtf(v1[tid] + BN_EPS);
        scl[tid]   = s;
        bias1[tid] = b1a[tid] * s + be1[tid] - m1[tid] * s;
        bias2[tid] = b1b[tid];
    }
    __syncthreads();
    for (int i = tid; i < 4096; i += 128) {
        Wa[i] = __float2half(W1a[i] * scl[i & 63]);
        Wb[i] = __float2half(W1b[i]);
    }
    __syncthreads();

    for (int n0 = blockIdx.x * 128; n0 < NN; n0 += gridDim.x * 128) {
        // load tile (fp16 rows, coalesced uint4)
        #pragma unroll
        for (int i = 0; i < 8; i++) {
            int idx = tid + i * 128;           // uint4 index; row = idx>>3
            int node = n0 + (idx >> 3);
            uint4 v = make_uint4(0, 0, 0, 0);
            if (node < NN) v = ((const uint4*)g_agg1h)[(size_t)n0 * 8 + idx];
            ((uint4*)Ah)[idx] = v;
        }
        __syncthreads();

        // ---- layer 1 (wmma) ----
        {
            wmma::fragment<wmma::accumulator, 16, 16, 16, float> acc[2][4];
            #pragma unroll
            for (int r = 0; r < 2; r++)
                #pragma unroll
                for (int c = 0; c < 4; c++) wmma::fill_fragment(acc[r][c], 0.f);
            #pragma unroll
            for (int kk = 0; kk < 4; kk++) {
                wmma::fragment<wmma::matrix_a, 16, 16, 16, __half, wmma::row_major> a[2];
                #pragma unroll
                for (int r = 0; r < 2; r++)
                    wmma::load_matrix_sync(a[r], Ah + (w * 32 + r * 16) * 64 + kk * 16, 64);
                #pragma unroll
                for (int c = 0; c < 4; c++) {
                    wmma::fragment<wmma::matrix_b, 16, 16, 16, __half, wmma::row_major> b;
                    wmma::load_matrix_sync(b, Wa + kk * 16 * 64 + c * 16, 64);
                    wmma::mma_sync(acc[0][c], a[0], b, acc[0][c]);
                    wmma::mma_sync(acc[1][c], a[1], b, acc[1][c]);
                }
            }
            #pragma unroll
            for (int r = 0; r < 2; r++)
                #pragma unroll
                for (int c = 0; c < 4; c++)
                    wmma::store_matrix_sync(Mid + (w * 32 + r * 16) * 64 + c * 16,
                                            acc[r][c], 64, wmma::mem_row_major);
        }
        __syncthreads();

        // bias + relu + convert -> Ah (half2 slots, conflict-free)
        #pragma unroll
        for (int i = 0; i < 32; i++) {
            int s = tid + i * 128;          // half2 slot
            int col2 = s & 31;
            float lo = fmaxf(Mid[s * 2]     + bias1[2 * col2],     0.f);
            float hi = fmaxf(Mid[s * 2 + 1] + bias1[2 * col2 + 1], 0.f);
            ((__half2*)Ah)[s] = __floats2half2_rn(lo, hi);
        }
        __syncthreads();

        // ---- layer 2 (wmma) ----
        {
            wmma::fragment<wmma::accumulator, 16, 16, 16, float> acc[2][4];
            #pragma unroll
            for (int r = 0; r < 2; r++)
                #pragma unroll
                for (int c = 0; c < 4; c++) wmma::fill_fragment(acc[r][c], 0.f);
            #pragma unroll
            for (int kk = 0; kk < 4; kk++) {
                wmma::fragment<wmma::matrix_a, 16, 16, 16, __half, wmma::row_major> a[2];
                #pragma unroll
                for (int r = 0; r < 2; r++)
                    wmma::load_matrix_sync(a[r], Ah + (w * 32 + r * 16) * 64 + kk * 16, 64);
                #pragma unroll
                for (int c = 0; c < 4; c++) {
                    wmma::fragment<wmma::matrix_b, 16, 16, 16, __half, wmma::row_major> b;
                    wmma::load_matrix_sync(b, Wb + kk * 16 * 64 + c * 16, 64);
                    wmma::mma_sync(acc[0][c], a[0], b, acc[0][c]);
                    wmma::mma_sync(acc[1][c], a[1], b, acc[1][c]);
                }
            }
            #pragma unroll
            for (int r = 0; r < 2; r++)
                #pragma unroll
                for (int c = 0; c < 4; c++)
                    wmma::store_matrix_sync(Mid + (w * 32 + r * 16) * 64 + c * 16,
                                            acc[r][c], 64, wmma::mem_row_major);
        }
        __syncthreads();

        // epilogue: bias + relu -> fp16 gmem
        #pragma unroll
        for (int i = 0; i < 32; i++) {
            int s = tid + i * 128;
            int row = s >> 5, col2 = s & 31;
            int node = n0 + row;
            if (node < NN) {
                float lo = fmaxf(Mid[s * 2]     + bias2[2 * col2],     0.f);
                float hi = fmaxf(Mid[s * 2 + 1] + bias2[2 * col2 + 1], 0.f);
                ((__half2*)g_h1bh)[(size_t)node * 32 + col2] = __floats2half2_rn(lo, hi);
            }
        }
        __syncthreads();
    }
}

// ---------------------------------------------------------------------------
// MLP2 (wmma) + pooling: h2 = relu(BN(agg2 @ W2 + b2)); xstruct[batch] += h2
// Dyn smem: W[4096]h + Ah[8192]h + Mid[8192]f = 56 KB.
// ---------------------------------------------------------------------------
__global__ __launch_bounds__(128) void mlp2_kernel(
    const float* __restrict__ W2, const float* __restrict__ b2,
    const float* __restrict__ g2, const float* __restrict__ be2,
    const float* __restrict__ m2, const float* __restrict__ v2,
    const int* __restrict__ batch)
{
    extern __shared__ char smraw[];
    __half* Ws  = (__half*)smraw;            // 64x64
    __half* Ah  = Ws + 4096;                 // 128x64
    float*  Mid = (float*)(Ah + 8192);       // 128x64
    __shared__ float bias[64], scl[64];

    const int tid  = threadIdx.x;
    const int w    = tid >> 5;

    if (tid < 64) {
        float s = g2[tid] * rsqrtf(v2[tid] + BN_EPS);
        scl[tid]  = s;
        bias[tid] = b2[tid] * s + be2[tid] - m2[tid] * s;
    }
    __syncthreads();
    for (int i = tid; i < 4096; i += 128)
        Ws[i] = __float2half(W2[i] * scl[i & 63]);
    __syncthreads();

    for (int n0 = blockIdx.x * 128; n0 < NN; n0 += gridDim.x * 128) {
        #pragma unroll
        for (int i = 0; i < 8; i++) {
            int idx = tid + i * 128;
            int node = n0 + (idx >> 3);
            uint4 v = make_uint4(0, 0, 0, 0);
            if (node < NN) v = ((const uint4*)g_agg2h)[(size_t)n0 * 8 + idx];
            ((uint4*)Ah)[idx] = v;
        }
        __syncthreads();

        {
            wmma::fragment<wmma::accumulator, 16, 16, 16, float> acc[2][4];
            #pragma unroll
            for (int r = 0; r < 2; r++)
                #pragma unroll
                for (int c = 0; c < 4; c++) wmma::fill_fragment(acc[r][c], 0.f);
            #pragma unroll
            for (int kk = 0; kk < 4; kk++) {
                wmma::fragment<wmma::matrix_a, 16, 16, 16, __half, wmma::row_major> a[2];
                #pragma unroll
                for (int r = 0; r < 2; r++)
                    wmma::load_matrix_sync(a[r], Ah + (w * 32 + r * 16) * 64 + kk * 16, 64);
                #pragma unroll
                for (int c = 0; c < 4; c++) {
                    wmma::fragment<wmma::matrix_b, 16, 16, 16, __half, wmma::row_major> b;
                    wmma::load_matrix_sync(b, Ws + kk * 16 * 64 + c * 16, 64);
                    wmma::mma_sync(acc[0][c], a[0], b, acc[0][c]);
                    wmma::mma_sync(acc[1][c], a[1], b, acc[1][c]);
                }
            }
            #pragma unroll
            for (int r = 0; r < 2; r++)
                #pragma unroll
                for (int c = 0; c < 4; c++)
                    wmma::store_matrix_sync(Mid + (w * 32 + r * 16) * 64 + c * 16,
                                            acc[r][c], 64, wmma::mem_row_major);
        }
        __syncthreads();

        // pooling epilogue: bias + relu -> red.add float4
        #pragma unroll
        for (int i = 0; i < 16; i++) {
            int s = tid + i * 128;          // float4 slot: 128 rows x 16
            int row = s >> 4, fq = s & 15;
            int node = n0 + row;
            if (node < NN) {
                float4 v;
                v.x = fmaxf(Mid[row * 64 + fq * 4]     + bias[fq * 4],     0.f);
                v.y = fmaxf(Mid[row * 64 + fq * 4 + 1] + bias[fq * 4 + 1], 0.f);
                v.z = fmaxf(Mid[row * 64 + fq * 4 + 2] + bias[fq * 4 + 2], 0.f);
                v.w = fmaxf(Mid[row * 64 + fq * 4 + 3] + bias[fq * 4 + 3], 0.f);
                int g = batch[node];
                red_add_v4(g_xstruct + (size_t)g * 64 + fq * 4, v);
            }
        }
        __syncthreads();
    }
}

// ---------------------------------------------------------------------------
// K6: x_topo = relu(topo @ Wt + bt); out = [xstruct, x_topo] @ Wc + bc
// ---------------------------------------------------------------------------
__global__ __launch_bounds__(256) void final_kernel(
    const float* __restrict__ topo, const float* __restrict__ Wt,
    const float* __restrict__ bt,   const float* __restrict__ Wc,
    const float* __restrict__ bc,   float* __restrict__ out)
{
    __shared__ float Wts[64 * 64];
    __shared__ float Wcs[128 * CC];
    __shared__ float bts[64], bcs[CC];
    __shared__ float trow[4][64];
    __shared__ float xt[4][64];
    __shared__ float xs[4][64];

    const int tx = threadIdx.x;   // 0..63
    const int ty = threadIdx.y;   // 0..3
    const int tid = ty * 64 + tx;

    for (int i = tid; i < 4096; i += 256) Wts[i] = Wt[i];
    for (int i = tid; i < 128 * CC; i += 256) Wcs[i] = Wc[i];
    if (tid < 64) bts[tid] = bt[tid];
    if (tid < CC) bcs[tid] = bc[tid];
    __syncthreads();

    for (int g0 = blockIdx.x * 4; g0 < BB; g0 += gridDim.x * 4) {
        int g = g0 + ty;
        bool valid = g < BB;
        if (valid) {
            trow[ty][tx] = topo[g * 64 + tx];
            xs[ty][tx]   = g_xstruct[g * 64 + tx];
        }
        __syncthreads();
        if (valid) {
            float acc = bts[tx];
            #pragma unroll 16
            for (int k = 0; k < 64; k++)
                acc += trow[ty][k] * Wts[k * 64 + tx];
            xt[ty][tx] = fmaxf(acc, 0.f);
        }
        __syncthreads();
        if (valid && tx < CC) {
            float acc = bcs[tx];
            #pragma unroll 16
            for (int k = 0; k < 64; k++) {
                acc += xs[ty][k] * Wcs[k * CC + tx];
                acc += xt[ty][k] * Wcs[(64 + k) * CC + tx];
            }
            out[g * CC + tx] = acc;
        }
        __syncthreads();
    }
}

// ---------------------------------------------------------------------------
extern "C" void kernel_launch(void* const* d_in, const int* in_sizes, int n_in,
                              void* d_out, int out_size) {
    const float* x    = (const float*)d_in[0];
    const int*   ei   = (const int*)d_in[1];
    const int*   batch= (const int*)d_in[2];
    const float* topo = (const float*)d_in[3];
    const float* W1a  = (const float*)d_in[4];
    const float* b1a  = (const float*)d_in[5];
    const float* g1   = (const float*)d_in[6];
    const float* be1  = (const float*)d_in[7];
    const float* m1   = (const float*)d_in[8];
    const float* v1   = (const float*)d_in[9];
    const float* W1b  = (const float*)d_in[10];
    const float* b1b  = (const float*)d_in[11];
    const float* W2   = (const float*)d_in[12];
    const float* b2   = (const float*)d_in[13];
    const float* g2   = (const float*)d_in[14];
    const float* be2  = (const float*)d_in[15];
    const float* m2   = (const float*)d_in[16];
    const float* v2   = (const float*)d_in[17];
    const float* Wt   = (const float*)d_in[18];
    const float* bt   = (const float*)d_in[19];
    const float* Wc   = (const float*)d_in[20];
    const float* bc   = (const float*)d_in[21];
    float* out = (float*)d_out;

    const int smem1 = 4096 * 2 + 4096 * 2 + 8192 * 2 + 8192 * 4;  // 64 KB
    const int smem2 = 4096 * 2 + 8192 * 2 + 8192 * 4;             // 56 KB
    static bool attr_set = false;
    if (!attr_set) {
        cudaFuncSetAttribute(mlp1_kernel,
                             cudaFuncAttributeMaxDynamicSharedMemorySize, smem1);
        cudaFuncSetAttribute(mlp2_kernel,
                             cudaFuncAttributeMaxDynamicSharedMemorySize, smem2);
        attr_set = true;
    }

    const int NB = (NN + 255) / 256;         // 391
    dim3 finBlock(64, 4);

    // CSR build + fp16 conversion
    prep_kernel<<<(NN * HH / 4 + 255) / 256, 256>>>(x);
    hist_kernel<<<(EE + 255) / 256, 256>>>(ei);
    bsum_kernel<<<NB, 256>>>();
    rowptr_kernel<<<NB, 256>>>();
    scatter_kernel<<<(EE + 255) / 256, 256>>>(ei);

    // Layer 1
    agg1_kernel<<<(NN * 16 + 255) / 256, 256>>>(x);
    mlp1_kernel<<<391, 128, smem1>>>(W1a, b1a, g1, be1, m1, v1, W1b, b1b);

    // Layer 2
    agg2_kernel<<<(NN * 16 + 255) / 256, 256>>>();
    mlp2_kernel<<<391, 128, smem2>>>(W2, b2, g2, be2, m2, v2, batch);

    final_kernel<<<64, finBlock>>>(topo, Wt, bt, Wc, bc, out);
}

// round 8
// speedup vs baseline: 1.6382x; 1.0209x over previous
#include <cuda_runtime.h>
#include <cuda_fp16.h>
#include <mma.h>

using namespace nvcuda;

#define NN 100000
#define EE 1200000
#define HH 64
#define BB 1000
#define CC 10
#define BN_EPS 1e-5f

typedef unsigned long long u64;

// Scratch (device globals; no allocation allowed)
__device__ __align__(16) __half g_xh[NN * HH];       // fp16 shadow of x
__device__ __align__(16) __half g_agg1h[NN * HH];    // fp16 agg of layer 1 input
__device__ __align__(16) __half g_h1bh[NN * HH];     // fp16 output of MLP1
__device__ __align__(16) __half g_agg2h[NN * HH];    // fp16 agg of layer 2 input
__device__ __align__(16) float  g_xstruct[BB * HH];  // pooled per-graph features
__device__ int g_deg[NN];
__device__ int g_rowptr[NN + 1];
__device__ int g_cursor[NN];
__device__ int g_bsum[512];
__device__ int g_csr[EE];

__device__ __forceinline__ void red_add_v4(float* p, float4 v) {
    asm volatile("red.global.add.v4.f32 [%0], {%1,%2,%3,%4};"
                 :: "l"(p), "f"(v.x), "f"(v.y), "f"(v.z), "f"(v.w)
                 : "memory");
}

// ---------------------------------------------------------------------------
// zero: deg + xstruct   (must precede hist on main stream)
// ---------------------------------------------------------------------------
__global__ void zero_kernel() {
    int i = blockIdx.x * 256 + threadIdx.x;
    if (i < NN) g_deg[i] = 0;
    if (i < BB * HH) g_xstruct[i] = 0.0f;
}

// convert x -> fp16 shadow (independent; runs on side stream)
__global__ void convert_kernel(const float* __restrict__ x) {
    int i = blockIdx.x * 256 + threadIdx.x;
    if (i < NN * HH / 4) {
        float4 v = *(const float4*)(x + (size_t)i * 4);
        __half2 h0 = __floats2half2_rn(v.x, v.y);
        __half2 h1 = __floats2half2_rn(v.z, v.w);
        uint2 u;
        u.x = *(unsigned*)&h0;
        u.y = *(unsigned*)&h1;
        *(uint2*)(g_xh + (size_t)i * 4) = u;
    }
}

__global__ void hist_kernel(const int* __restrict__ ei) {
    int e = blockIdx.x * 256 + threadIdx.x;
    if (e < EE) atomicAdd(&g_deg[ei[EE + e]], 1);
}

__global__ void bsum_kernel() {   // 391 blocks x 256, raw block sums
    __shared__ int sh[256];
    int i = blockIdx.x * 256 + threadIdx.x;
    int t = threadIdx.x;
    sh[t] = (i < NN) ? g_deg[i] : 0;
    __syncthreads();
    for (int off = 128; off > 0; off >>= 1) {
        if (t < off) sh[t] += sh[t + off];
        __syncthreads();
    }
    if (t == 0) g_bsum[blockIdx.x] = sh[0];
}

// rowptr: inline prefix over raw block sums
__global__ void rowptr_kernel() {   // 391 blocks x 256
    __shared__ int sh[256];
    __shared__ int red[256];
    int i = blockIdx.x * 256 + threadIdx.x;
    int t = threadIdx.x;

    int pre = 0;
    for (int b = t; b < blockIdx.x; b += 256) pre += g_bsum[b];
    red[t] = pre;
    __syncthreads();
    for (int off = 128; off > 0; off >>= 1) {
        if (t < off) red[t] += red[t + off];
        __syncthreads();
    }
    int base = red[0];

    int v = (i < NN) ? g_deg[i] : 0;
    sh[t] = v;
    __syncthreads();
    for (int off = 1; off < 256; off <<= 1) {
        int a = (t >= off) ? sh[t - off] : 0;
        __syncthreads();
        sh[t] += a;
        __syncthreads();
    }
    if (i < NN) {
        int r = base + sh[t] - v;   // exclusive
        g_rowptr[i] = r;
        g_cursor[i] = r;
    }
    if (i == 0) g_rowptr[NN] = EE;
}

// cursor-based scatter (atomic bump; cheap at 100k distinct addresses)
__global__ void scatter_kernel(const int* __restrict__ ei) {
    int e = blockIdx.x * 256 + threadIdx.x;
    if (e < EE) {
        int s = ei[e];
        int d = ei[EE + e];
        int pos = atomicAdd(&g_cursor[d], 1);
        g_csr[pos] = s;
    }
}

// ---------------------------------------------------------------------------
// Pull aggregation: 8 threads/node, each owns 8 cols (16 B per neighbor row).
// fp16 gather, fp32 accumulate, fp16 output. Neighbor loop unrolled x4.
// ---------------------------------------------------------------------------
__device__ __forceinline__ void acc_half8(float* acc, const __half* p) {
    uint4 u = *(const uint4*)p;
    __half2* h = (__half2*)&u;
    #pragma unroll
    for (int i = 0; i < 4; i++) {
        float2 f = __half22float2(h[i]);
        acc[2 * i]     += f.x;
        acc[2 * i + 1] += f.y;
    }
}

__device__ __forceinline__ void store_half8(__half* p, const float* acc) {
    uint4 u;
    unsigned* w = (unsigned*)&u;
    #pragma unroll
    for (int i = 0; i < 4; i++) {
        __half2 h = __floats2half2_rn(acc[2 * i], acc[2 * i + 1]);
        w[i] = *(unsigned*)&h;
    }
    *(uint4*)p = u;
}

__global__ __launch_bounds__(256) void agg1_kernel(const float* __restrict__ x)
{
    int tid = blockIdx.x * 256 + threadIdx.x;
    int node = tid >> 3;
    if (node >= NN) return;
    int c = (tid & 7) * 8;

    float acc[8];
    {   // self term exact fp32
        float4 a = *(const float4*)(x + (size_t)node * 64 + c);
        float4 b = *(const float4*)(x + (size_t)node * 64 + c + 4);
        acc[0] = a.x; acc[1] = a.y; acc[2] = a.z; acc[3] = a.w;
        acc[4] = b.x; acc[5] = b.y; acc[6] = b.z; acc[7] = b.w;
    }
    int j = g_rowptr[node];
    int e = g_rowptr[node + 1];
    for (; j + 3 < e; j += 4) {
        int s0 = g_csr[j],     s1 = g_csr[j + 1];
        int s2 = g_csr[j + 2], s3 = g_csr[j + 3];
        acc_half8(acc, g_xh + (size_t)s0 * 64 + c);
        acc_half8(acc, g_xh + (size_t)s1 * 64 + c);
        acc_half8(acc, g_xh + (size_t)s2 * 64 + c);
        acc_half8(acc, g_xh + (size_t)s3 * 64 + c);
    }
    for (; j < e; j++)
        acc_half8(acc, g_xh + (size_t)g_csr[j] * 64 + c);
    store_half8(g_agg1h + (size_t)node * 64 + c, acc);
}

__global__ __launch_bounds__(256) void agg2_kernel()
{
    int tid = blockIdx.x * 256 + threadIdx.x;
    int node = tid >> 3;
    if (node >= NN) return;
    int c = (tid & 7) * 8;

    float acc[8] = {0.f, 0.f, 0.f, 0.f, 0.f, 0.f, 0.f, 0.f};
    acc_half8(acc, g_h1bh + (size_t)node * 64 + c);   // self
    int j = g_rowptr[node];
    int e = g_rowptr[node + 1];
    for (; j + 3 < e; j += 4) {
        int s0 = g_csr[j],     s1 = g_csr[j + 1];
        int s2 = g_csr[j + 2], s3 = g_csr[j + 3];
        acc_half8(acc, g_h1bh + (size_t)s0 * 64 + c);
        acc_half8(acc, g_h1bh + (size_t)s1 * 64 + c);
        acc_half8(acc, g_h1bh + (size_t)s2 * 64 + c);
        acc_half8(acc, g_h1bh + (size_t)s3 * 64 + c);
    }
    for (; j < e; j++)
        acc_half8(acc, g_h1bh + (size_t)g_csr[j] * 64 + c);
    store_half8(g_agg2h + (size_t)node * 64 + c, acc);
}

// ---------------------------------------------------------------------------
// MLP1 (wmma): h1bh = fp16(relu( relu(BN(agg1 @ W1a + b1a)) @ W1b + b1b ))
// ---------------------------------------------------------------------------
__global__ __launch_bounds__(128) void mlp1_kernel(
    const float* __restrict__ W1a, const float* __restrict__ b1a,
    const float* __restrict__ g1,  const float* __restrict__ be1,
    const float* __restrict__ m1,  const float* __restrict__ v1,
    const float* __restrict__ W1b, const float* __restrict__ b1b)
{
    extern __shared__ char smraw[];
    __half* Wa  = (__half*)smraw;            // 64x64
    __half* Wb  = Wa + 4096;                 // 64x64
    __half* Ah  = Wb + 4096;                 // 128x64
    float*  Mid = (float*)(Ah + 8192);       // 128x64
    __shared__ float bias1[64], bias2[64], scl[64];

    const int tid  = threadIdx.x;
    const int w    = tid >> 5;

    if (tid < 64) {
        float s = g1[tid] * rsqrtf(v1[tid] + BN_EPS);
        scl[tid]   = s;
        bias1[tid] = b1a[tid] * s + be1[tid] - m1[tid] * s;
        bias2[tid] = b1b[tid];
    }
    __syncthreads();
    for (int i = tid; i < 4096; i += 128) {
        Wa[i] = __float2half(W1a[i] * scl[i & 63]);
        Wb[i] = __float2half(W1b[i]);
    }
    __syncthreads();

    for (int n0 = blockIdx.x * 128; n0 < NN; n0 += gridDim.x * 128) {
        #pragma unroll
        for (int i = 0; i < 8; i++) {
            int idx = tid + i * 128;
            int node = n0 + (idx >> 3);
            uint4 v = make_uint4(0, 0, 0, 0);
            if (node < NN) v = ((const uint4*)g_agg1h)[(size_t)n0 * 8 + idx];
            ((uint4*)Ah)[idx] = v;
        }
        __syncthreads();

        // ---- layer 1 (wmma) ----
        {
            wmma::fragment<wmma::accumulator, 16, 16, 16, float> acc[2][4];
            #pragma unroll
            for (int r = 0; r < 2; r++)
                #pragma unroll
                for (int c = 0; c < 4; c++) wmma::fill_fragment(acc[r][c], 0.f);
            #pragma unroll
            for (int kk = 0; kk < 4; kk++) {
                wmma::fragment<wmma::matrix_a, 16, 16, 16, __half, wmma::row_major> a[2];
                #pragma unroll
                for (int r = 0; r < 2; r++)
                    wmma::load_matrix_sync(a[r], Ah + (w * 32 + r * 16) * 64 + kk * 16, 64);
                #pragma unroll
                for (int c = 0; c < 4; c++) {
                    wmma::fragment<wmma::matrix_b, 16, 16, 16, __half, wmma::row_major> b;
                    wmma::load_matrix_sync(b, Wa + kk * 16 * 64 + c * 16, 64);
                    wmma::mma_sync(acc[0][c], a[0], b, acc[0][c]);
                    wmma::mma_sync(acc[1][c], a[1], b, acc[1][c]);
                }
            }
            #pragma unroll
            for (int r = 0; r < 2; r++)
                #pragma unroll
                for (int c = 0; c < 4; c++)
                    wmma::store_matrix_sync(Mid + (w * 32 + r * 16) * 64 + c * 16,
                                            acc[r][c], 64, wmma::mem_row_major);
        }
        __syncthreads();

        // bias + relu + convert -> Ah
        #pragma unroll
        for (int i = 0; i < 32; i++) {
            int s = tid + i * 128;
            int col2 = s & 31;
            float lo = fmaxf(Mid[s * 2]     + bias1[2 * col2],     0.f);
            float hi = fmaxf(Mid[s * 2 + 1] + bias1[2 * col2 + 1], 0.f);
            ((__half2*)Ah)[s] = __floats2half2_rn(lo, hi);
        }
        __syncthreads();

        // ---- layer 2 (wmma) ----
        {
            wmma::fragment<wmma::accumulator, 16, 16, 16, float> acc[2][4];
            #pragma unroll
            for (int r = 0; r < 2; r++)
                #pragma unroll
                for (int c = 0; c < 4; c++) wmma::fill_fragment(acc[r][c], 0.f);
            #pragma unroll
            for (int kk = 0; kk < 4; kk++) {
                wmma::fragment<wmma::matrix_a, 16, 16, 16, __half, wmma::row_major> a[2];
                #pragma unroll
                for (int r = 0; r < 2; r++)
                    wmma::load_matrix_sync(a[r], Ah + (w * 32 + r * 16) * 64 + kk * 16, 64);
                #pragma unroll
                for (int c = 0; c < 4; c++) {
                    wmma::fragment<wmma::matrix_b, 16, 16, 16, __half, wmma::row_major> b;
                    wmma::load_matrix_sync(b, Wb + kk * 16 * 64 + c * 16, 64);
                    wmma::mma_sync(acc[0][c], a[0], b, acc[0][c]);
                    wmma::mma_sync(acc[1][c], a[1], b, acc[1][c]);
                }
            }
            #pragma unroll
            for (int r = 0; r < 2; r++)
                #pragma unroll
                for (int c = 0; c < 4; c++)
                    wmma::store_matrix_sync(Mid + (w * 32 + r * 16) * 64 + c * 16,
                                            acc[r][c], 64, wmma::mem_row_major);
        }
        __syncthreads();

        #pragma unroll
        for (int i = 0; i < 32; i++) {
            int s = tid + i * 128;
            int row = s >> 5, col2 = s & 31;
            int node = n0 + row;
            if (node < NN) {
                float lo = fmaxf(Mid[s * 2]     + bias2[2 * col2],     0.f);
                float hi = fmaxf(Mid[s * 2 + 1] + bias2[2 * col2 + 1], 0.f);
                ((__half2*)g_h1bh)[(size_t)node * 32 + col2] = __floats2half2_rn(lo, hi);
            }
        }
        __syncthreads();
    }
}

// ---------------------------------------------------------------------------
// MLP2 (wmma) + pooling
// ---------------------------------------------------------------------------
__global__ __launch_bounds__(128) void mlp2_kernel(
    const float* __restrict__ W2, const float* __restrict__ b2,
    const float* __restrict__ g2, const float* __restrict__ be2,
    const float* __restrict__ m2, const float* __restrict__ v2,
    const int* __restrict__ batch)
{
    extern __shared__ char smraw[];
    __half* Ws  = (__half*)smraw;            // 64x64
    __half* Ah  = Ws + 4096;                 // 128x64
    float*  Mid = (float*)(Ah + 8192);       // 128x64
    __shared__ float bias[64], scl[64];

    const int tid  = threadIdx.x;
    const int w    = tid >> 5;

    if (tid < 64) {
        float s = g2[tid] * rsqrtf(v2[tid] + BN_EPS);
        scl[tid]  = s;
        bias[tid] = b2[tid] * s + be2[tid] - m2[tid] * s;
    }
    __syncthreads();
    for (int i = tid; i < 4096; i += 128)
        Ws[i] = __float2half(W2[i] * scl[i & 63]);
    __syncthreads();

    for (int n0 = blockIdx.x * 128; n0 < NN; n0 += gridDim.x * 128) {
        #pragma unroll
        for (int i = 0; i < 8; i++) {
            int idx = tid + i * 128;
            int node = n0 + (idx >> 3);
            uint4 v = make_uint4(0, 0, 0, 0);
            if (node < NN) v = ((const uint4*)g_agg2h)[(size_t)n0 * 8 + idx];
            ((uint4*)Ah)[idx] = v;
        }
        __syncthreads();

        {
            wmma::fragment<wmma::accumulator, 16, 16, 16, float> acc[2][4];
            #pragma unroll
            for (int r = 0; r < 2; r++)
                #pragma unroll
                for (int c = 0; c < 4; c++) wmma::fill_fragment(acc[r][c], 0.f);
            #pragma unroll
            for (int kk = 0; kk < 4; kk++) {
                wmma::fragment<wmma::matrix_a, 16, 16, 16, __half, wmma::row_major> a[2];
                #pragma unroll
                for (int r = 0; r < 2; r++)
                    wmma::load_matrix_sync(a[r], Ah + (w * 32 + r * 16) * 64 + kk * 16, 64);
                #pragma unroll
                for (int c = 0; c < 4; c++) {
                    wmma::fragment<wmma::matrix_b, 16, 16, 16, __half, wmma::row_major> b;
                    wmma::load_matrix_sync(b, Ws + kk * 16 * 64 + c * 16, 64);
                    wmma::mma_sync(acc[0][c], a[0], b, acc[0][c]);
                    wmma::mma_sync(acc[1][c], a[1], b, acc[1][c]);
                }
            }
            #pragma unroll
            for (int r = 0; r < 2; r++)
                #pragma unroll
                for (int c = 0; c < 4; c++)
                    wmma::store_matrix_sync(Mid + (w * 32 + r * 16) * 64 + c * 16,
                                            acc[r][c], 64, wmma::mem_row_major);
        }
        __syncthreads();

        #pragma unroll
        for (int i = 0; i < 16; i++) {
            int s = tid + i * 128;
            int row = s >> 4, fq = s & 15;
            int node = n0 + row;
            if (node < NN) {
                float4 v;
                v.x = fmaxf(Mid[row * 64 + fq * 4]     + bias[fq * 4],     0.f);
                v.y = fmaxf(Mid[row * 64 + fq * 4 + 1] + bias[fq * 4 + 1], 0.f);
                v.z = fmaxf(Mid[row * 64 + fq * 4 + 2] + bias[fq * 4 + 2], 0.f);
                v.w = fmaxf(Mid[row * 64 + fq * 4 + 3] + bias[fq * 4 + 3], 0.f);
                int g = batch[node];
                red_add_v4(g_xstruct + (size_t)g * 64 + fq * 4, v);
            }
        }
        __syncthreads();
    }
}

// ---------------------------------------------------------------------------
// K6: x_topo = relu(topo @ Wt + bt); out = [xstruct, x_topo] @ Wc + bc
// ---------------------------------------------------------------------------
__global__ __launch_bounds__(256) void final_kernel(
    const float* __restrict__ topo, const float* __restrict__ Wt,
    const float* __restrict__ bt,   const float* __restrict__ Wc,
    const float* __restrict__ bc,   float* __restrict__ out)
{
    __shared__ float Wts[64 * 64];
    __shared__ float Wcs[128 * CC];
    __shared__ float bts[64], bcs[CC];
    __shared__ float trow[4][64];
    __shared__ float xt[4][64];
    __shared__ float xs[4][64];

    const int tx = threadIdx.x;   // 0..63
    const int ty = threadIdx.y;   // 0..3
    const int tid = ty * 64 + tx;

    for (int i = tid; i < 4096; i += 256) Wts[i] = Wt[i];
    for (int i = tid; i < 128 * CC; i += 256) Wcs[i] = Wc[i];
    if (tid < 64) bts[tid] = bt[tid];
    if (tid < CC) bcs[tid] = bc[tid];
    __syncthreads();

    for (int g0 = blockIdx.x * 4; g0 < BB; g0 += gridDim.x * 4) {
        int g = g0 + ty;
        bool valid = g < BB;
        if (valid) {
            trow[ty][tx] = topo[g * 64 + tx];
            xs[ty][tx]   = g_xstruct[g * 64 + tx];
        }
        __syncthreads();
        if (valid) {
            float acc = bts[tx];
            #pragma unroll 16
            for (int k = 0; k < 64; k++)
                acc += trow[ty][k] * Wts[k * 64 + tx];
            xt[ty][tx] = fmaxf(acc, 0.f);
        }
        __syncthreads();
        if (valid && tx < CC) {
            float acc = bcs[tx];
            #pragma unroll 16
            for (int k = 0; k < 64; k++) {
                acc += xs[ty][k] * Wcs[k * CC + tx];
                acc += xt[ty][k] * Wcs[(64 + k) * CC + tx];
            }
            out[g * CC + tx] = acc;
        }
        __syncthreads();
    }
}

// ---------------------------------------------------------------------------
extern "C" void kernel_launch(void* const* d_in, const int* in_sizes, int n_in,
                              void* d_out, int out_size) {
    const float* x    = (const float*)d_in[0];
    const int*   ei   = (const int*)d_in[1];
    const int*   batch= (const int*)d_in[2];
    const float* topo = (const float*)d_in[3];
    const float* W1a  = (const float*)d_in[4];
    const float* b1a  = (const float*)d_in[5];
    const float* g1   = (const float*)d_in[6];
    const float* be1  = (const float*)d_in[7];
    const float* m1   = (const float*)d_in[8];
    const float* v1   = (const float*)d_in[9];
    const float* W1b  = (const float*)d_in[10];
    const float* b1b  = (const float*)d_in[11];
    const float* W2   = (const float*)d_in[12];
    const float* b2   = (const float*)d_in[13];
    const float* g2   = (const float*)d_in[14];
    const float* be2  = (const float*)d_in[15];
    const float* m2   = (const float*)d_in[16];
    const float* v2   = (const float*)d_in[17];
    const float* Wt   = (const float*)d_in[18];
    const float* bt   = (const float*)d_in[19];
    const float* Wc   = (const float*)d_in[20];
    const float* bc   = (const float*)d_in[21];
    float* out = (float*)d_out;

    const int smem1 = 4096 * 2 + 4096 * 2 + 8192 * 2 + 8192 * 4;  // 64 KB
    const int smem2 = 4096 * 2 + 8192 * 2 + 8192 * 4;             // 56 KB

    static cudaStream_t s2;
    static cudaEvent_t evFork, evJoin;
    static bool init_done = false;
    if (!init_done) {
        cudaFuncSetAttribute(mlp1_kernel,
                             cudaFuncAttributeMaxDynamicSharedMemorySize, smem1);
        cudaFuncSetAttribute(mlp2_kernel,
                             cudaFuncAttributeMaxDynamicSharedMemorySize, smem2);
        cudaStreamCreateWithFlags(&s2, cudaStreamNonBlocking);
        cudaEventCreateWithFlags(&evFork, cudaEventDisableTiming);
        cudaEventCreateWithFlags(&evJoin, cudaEventDisableTiming);
        init_done = true;
    }

    const int NB = (NN + 255) / 256;         // 391
    dim3 finBlock(64, 4);

    // Fork: fp16 conversion of x runs concurrently with CSR build
    cudaEventRecord(evFork, 0);
    cudaStreamWaitEvent(s2, evFork, 0);
    convert_kernel<<<(NN * HH / 4 + 255) / 256, 256, 0, s2>>>(x);
    cudaEventRecord(evJoin, s2);

    // CSR build (main stream)
    zero_kernel<<<NB, 256>>>();
    hist_kernel<<<(EE + 255) / 256, 256>>>(ei);
    bsum_kernel<<<NB, 256>>>();
    rowptr_kernel<<<NB, 256>>>();
    scatter_kernel<<<(EE + 255) / 256, 256>>>(ei);

    // Join before layer 1 (needs g_xh + CSR)
    cudaStreamWaitEvent(0, evJoin, 0);

    // Layer 1
    agg1_kernel<<<(NN * 8 + 255) / 256, 256>>>(x);
    mlp1_kernel<<<391, 128, smem1>>>(W1a, b1a, g1, be1, m1, v1, W1b, b1b);

    // Layer 2
    agg2_kernel<<<(NN * 8 + 255) / 256, 256>>>();
    mlp2_kernel<<<391, 128, smem2>>>(W2, b2, g2, be2, m2, v2, batch);

    final_kernel<<<64, finBlock>>>(topo, Wt, bt, Wc, bc, out);
}